// round 11
// baseline (speedup 1.0000x reference)
#include <cuda_runtime.h>

// GADBase guided anisotropic diffusion — persistent kernel v3.
// Tile 32 cols x 256 rows, 512 threads (16 warps), lane = column, thread = 16
// scalar rows in registers. 256 CTAs at 2/SM (1024 thr/SM, 64-reg cap, no
// spills). Conductances in SMEM (scalar access, 1 crossbar cyc/warp). Warp
// covers full tile width -> in-warp ratio reduction, 1 syncthreads/iter.

#define NPIX   (1024*1024)
#define CV_OFF 2097152
#define CH_OFF 4192256
#define GXT 32
#define GYT 4
#define NCTA (2*GXT*GYT)        // 256

// dynamic SMEM layout (floats)
#define OFF_A    0              // 257*32 = 8224 : 0.24*cv, row-boundary major
#define OFF_C    8224           // 256*33 = 8448 : 0.24*ch, stride 33, col 0 = left pad
#define OFF_TB   16672          // [2 par][16 w][2 t/b][32 lane] = 2048
#define OFF_WL   18720          // 256 : staged west edge cols
#define OFF_ER   18976          // 256 : staged east edge cols
#define OFF_SRC  19232          // 128
#define OFF_MSK  19360          // 128
#define SMEMF    19488          // 77952 bytes

__device__ float g_shift;
__device__ int   g_flag[NCTA];
__device__ float g_brow[2][2][GYT][2][1024];   // [parity][batch][tyr][top/bot][col]
__device__ float g_bcol[2][2][GXT][2][1024];   // [parity][batch][bx][left/right][row]

// ---------------------------------------------------------------------------
__global__ void k_pre(const float* __restrict__ src)
{
    __shared__ float red[32];
    int tid = threadIdx.x;                       // 1024 threads
    float mn = 1e30f;
    for (int i = tid; i < 2*128*128; i += 1024) mn = fminf(mn, src[i]);
    #pragma unroll
    for (int o = 16; o; o >>= 1) mn = fminf(mn, __shfl_xor_sync(~0u, mn, o));
    if ((tid & 31) == 0) red[tid >> 5] = mn;
    __syncthreads();
    if (tid < 32) {
        float v = red[tid];
        #pragma unroll
        for (int o = 16; o; o >>= 1) v = fminf(v, __shfl_xor_sync(~0u, v, o));
        if (tid == 0) g_shift = (v <= 0.1f) ? 0.1f : 0.0f;
    }
    if (tid < NCTA) g_flag[tid] = -1;
}

// ---------------------------------------------------------------------------
__device__ __forceinline__ void spin_ge(const int* p, int t)
{
    int v;
    do {
        asm volatile("ld.acquire.gpu.global.s32 %0, [%1];"
                     : "=r"(v) : "l"(p) : "memory");
    } while (v < t);
}

__device__ __forceinline__ void flag_release(int* p, int val)
{
    int old;
    asm volatile("atom.release.gpu.global.exch.b32 %0, [%1], %2;"
                 : "=r"(old) : "l"(p), "r"(val) : "memory");
}

extern __shared__ float sm[];

__global__ void __launch_bounds__(512, 2)
k_diffuse(const float* __restrict__ guide, const float* __restrict__ y,
          const float* __restrict__ src,   const float* __restrict__ mask,
          float* __restrict__ out)
{
    const int tid  = threadIdx.x;
    const int w    = tid >> 5, lane = tid & 31;
    const int bx = blockIdx.x, tyr = blockIdx.y, b = blockIdx.z;
    const int rowbase = tyr*256;
    const int gc  = bx*32 + lane;
    const int gr0 = rowbase + 16*w;
    const int cid = (b*GYT + tyr)*GXT + bx;
    const float shift = g_shift;
    const float K2 = 0.03f*0.03f;

    float v[16];

    // ======================= prologue ======================================
    const float* G0 = guide + b*3*NPIX;
    const float* G1 = G0 + NPIX;
    const float* G2 = G1 + NPIX;
    const float* Yp = y + b*NPIX;

    float p0 = 0.f, p1 = 0.f, p2 = 0.f, py = 0.f;
    #pragma unroll
    for (int j = 0; j < 18; j++) {
        int row = gr0 - 1 + j;
        bool inr = (unsigned)row < 1024u;
        int off = row*1024 + gc;
        float q0 = 0.f, q1 = 0.f, q2 = 0.f, qy = 0.f;
        if (inr) { q0 = G0[off]; q1 = G1[off]; q2 = G2[off]; qy = Yp[off]; }
        // right-neighbor column values (for ch)
        float r0v = __shfl_down_sync(~0u, q0, 1);
        float r1v = __shfl_down_sync(~0u, q1, 1);
        float r2v = __shfl_down_sync(~0u, q2, 1);
        float ryv = __shfl_down_sync(~0u, qy, 1);
        if (lane == 31 && inr && gc + 1 < 1024) {
            r0v = G0[off+1]; r1v = G1[off+1]; r2v = G2[off+1]; ryv = Yp[off+1];
        }
        if (j >= 1) {                                   // vertical boundary row-1/row
            int brow = row - 1;
            float av = 0.f;
            if ((unsigned)brow < 1023u) {
                float s = 0.25f*(fabsf(q0-p0)+fabsf(q1-p1)+fabsf(q2-p2)+fabsf(qy-py));
                float cv = 1.f/(1.f + s*s/K2);
                if (j >= 2)                             // ownership brow in [gr0, gr0+15]
                    out[CV_OFF + b*(1023*1024) + brow*1024 + gc] = cv;
                av = 0.24f*cv;
            }
            sm[OFF_A + (16*w - 1 + j)*32 + lane] = av;  // s_a[16w .. 16w+16]
        }
        if (j >= 1 && j <= 16) {
            int i = j - 1;                              // local row
            v[i] = qy + shift;
            float chv = 0.f;
            if (gc < 1023) {
                float s = 0.25f*(fabsf(r0v-q0)+fabsf(r1v-q1)+fabsf(r2v-q2)+fabsf(ryv-qy));
                chv = 1.f/(1.f + s*s/K2);
                out[CH_OFF + b*(1024*1023) + row*1023 + gc] = chv;
            }
            sm[OFF_C + (16*w + i)*33 + 1 + lane] = 0.24f*chv;
            if (lane == 0) {                            // left pad = west ch
                float clv = 0.f;
                if (bx > 0) {
                    float l0 = G0[off-1], l1 = G1[off-1], l2 = G2[off-1], ly = Yp[off-1];
                    float s = 0.25f*(fabsf(q0-l0)+fabsf(q1-l1)+fabsf(q2-l2)+fabsf(qy-ly));
                    clv = 0.24f/(1.f + s*s/K2);
                }
                sm[OFF_C + (16*w + i)*33] = clv;
            }
        }
        p0 = q0; p1 = q1; p2 = q2; py = qy;
    }

    if (tid < 128) {                                    // 32 block-rows x 4 block-cols
        int br = tid >> 2, bc = tid & 3;
        int bi = b*16384 + (tyr*32 + br)*128 + (bx*4 + bc);
        sm[OFF_SRC + tid] = src[bi] + shift;
        sm[OFF_MSK + tid] = (mask[bi] < 0.5f) ? 0.f : 1.f;
    }

    // publish state-0 boundaries (parity 0)
    sm[OFF_TB + ((0*16 + w)*2 + 0)*32 + lane] = v[0];
    sm[OFF_TB + ((0*16 + w)*2 + 1)*32 + lane] = v[15];
    if (w == 0  && tyr > 0)       g_brow[0][b][tyr][0][gc] = v[0];
    if (w == 15 && tyr < GYT - 1) g_brow[0][b][tyr][1][gc] = v[15];
    if (lane == 0 && bx > 0) {
        #pragma unroll
        for (int i = 0; i < 16; i++) g_bcol[0][b][bx][0][rowbase + 16*w + i] = v[i];
    }
    if (lane == 31 && bx < GXT - 1) {
        #pragma unroll
        for (int i = 0; i < 16; i++) g_bcol[0][b][bx][1][rowbase + 16*w + i] = v[i];
    }
    __syncthreads();
    if (tid == 0) flag_release(&g_flag[cid], 0);

    const bool hw = (bx > 0), he = (bx < GXT - 1);
    const int bidx_t = (2*w    )*4 + (lane >> 3);
    const int bidx_b = (2*w + 1)*4 + (lane >> 3);

    // ======================= 64 diffusion iterations =======================
    for (int t = 0; t < 64; t++) {
        int par = t & 1;

        // vertical halo
        float up, dn;
        if (w == 0) {
            if (tyr > 0) { spin_ge(&g_flag[cid - GXT], t);
                           up = __ldcg(&g_brow[par][b][tyr-1][1][gc]); }
            else up = 0.f;
        } else up = sm[OFF_TB + ((par*16 + w - 1)*2 + 1)*32 + lane];
        if (w == 15) {
            if (tyr < GYT - 1) { spin_ge(&g_flag[cid + GXT], t);
                                 dn = __ldcg(&g_brow[par][b][tyr+1][0][gc]); }
            else dn = 0.f;
        } else dn = sm[OFF_TB + ((par*16 + w + 1)*2 + 0)*32 + lane];

        // stage west/east edge columns into smem scratch (self-read only)
        if (lane == 0 && hw) {
            spin_ge(&g_flag[cid - 1], t);
            const float* wr = &g_bcol[par][b][bx-1][1][rowbase + 16*w];
            #pragma unroll
            for (int i = 0; i < 16; i++) sm[OFF_WL + 16*w + i] = __ldcg(wr + i);
        }
        if (lane == 31 && he) {
            spin_ge(&g_flag[cid + 1], t);
            const float* er = &g_bcol[par][b][bx+1][0][rowbase + 16*w];
            #pragma unroll
            for (int i = 0; i < 16; i++) sm[OFF_ER + 16*w + i] = __ldcg(er + i);
        }

        // stencil
        float pv = up;
        float a0 = sm[OFF_A + (16*w)*32 + lane];
        float acc_t = 0.f, acc_b = 0.f;
        #pragma unroll
        for (int i = 0; i < 16; i++) {
            float cur  = v[i];
            float down = (i < 15) ? v[i+1] : dn;
            float a1 = sm[OFF_A + (16*w + i + 1)*32 + lane];
            float c  = sm[OFF_C + (16*w + i)*33 + 1 + lane];
            float cl = sm[OFF_C + (16*w + i)*33 + lane];       // lane-1's c / west pad
            float lf = __shfl_up_sync(~0u, cur, 1);
            if (lane == 0)  lf = hw ? sm[OFF_WL + 16*w + i] : 0.f;
            float rt = __shfl_down_sync(~0u, cur, 1);
            if (lane == 31) rt = he ? sm[OFF_ER + 16*w + i] : 0.f;
            float nv = cur + (a1*(down - cur) - a0*(cur - pv)
                            + c*(rt - cur)    - cl*(cur - lf));
            v[i] = nv;
            pv = cur; a0 = a1;
            if (i < 8) acc_t += nv; else acc_b += nv;
        }

        // 8x8 block sums fully in-warp (8-lane groups), redundant ratio calc
        float st = acc_t, sb = acc_b;
        st += __shfl_xor_sync(~0u, st, 1);
        st += __shfl_xor_sync(~0u, st, 2);
        st += __shfl_xor_sync(~0u, st, 4);
        sb += __shfl_xor_sync(~0u, sb, 1);
        sb += __shfl_xor_sync(~0u, sb, 2);
        sb += __shfl_xor_sync(~0u, sb, 4);
        float ratio_t = (sm[OFF_MSK + bidx_t] != 0.f)
                      ? __fdividef(sm[OFF_SRC + bidx_t], st*(1.f/64.f) + 1e-8f) : 1.f;
        float ratio_b = (sm[OFF_MSK + bidx_b] != 0.f)
                      ? __fdividef(sm[OFF_SRC + bidx_b], sb*(1.f/64.f) + 1e-8f) : 1.f;
        #pragma unroll
        for (int i = 0; i < 8;  i++) v[i] *= ratio_t;
        #pragma unroll
        for (int i = 8; i < 16; i++) v[i] *= ratio_b;

        if (t == 63) break;

        // publish state t+1
        int pn = par ^ 1;
        sm[OFF_TB + ((pn*16 + w)*2 + 0)*32 + lane] = v[0];
        sm[OFF_TB + ((pn*16 + w)*2 + 1)*32 + lane] = v[15];
        if (w == 0  && tyr > 0)       __stcg(&g_brow[pn][b][tyr][0][gc], v[0]);
        if (w == 15 && tyr < GYT - 1) __stcg(&g_brow[pn][b][tyr][1][gc], v[15]);
        if (lane == 0 && hw) {
            #pragma unroll
            for (int i = 0; i < 16; i++)
                __stcg(&g_bcol[pn][b][bx][0][rowbase + 16*w + i], v[i]);
        }
        if (lane == 31 && he) {
            #pragma unroll
            for (int i = 0; i < 16; i++)
                __stcg(&g_bcol[pn][b][bx][1][rowbase + 16*w + i], v[i]);
        }
        __syncthreads();                 // CTA publishes done (cumulative for release)
        if (tid == 0) flag_release(&g_flag[cid], t + 1);
    }

    // ======================= epilogue ======================================
    #pragma unroll
    for (int i = 0; i < 16; i++)
        out[b*NPIX + (gr0 + i)*1024 + gc] = v[i] - shift;
}

// ---------------------------------------------------------------------------
extern "C" void kernel_launch(void* const* d_in, const int* in_sizes, int n_in,
                              void* d_out, int out_size)
{
    const float* guide = (const float*)d_in[0];
    const float* y     = (const float*)d_in[1];
    const float* src   = (const float*)d_in[2];
    const float* mask  = (const float*)d_in[3];
    float* out = (float*)d_out;

    cudaFuncSetAttribute(k_diffuse, cudaFuncAttributeMaxDynamicSharedMemorySize,
                         SMEMF * sizeof(float));

    k_pre<<<1, 1024>>>(src);
    dim3 g(GXT, GYT, 2);                // 256 CTAs — 2/SM, all co-resident
    k_diffuse<<<g, 512, SMEMF * sizeof(float)>>>(guide, y, src, mask, out);
}

// round 12
// speedup vs baseline: 1.7638x; 1.7638x over previous
#include <cuda_runtime.h>

// GADBase guided anisotropic diffusion — persistent kernel v4.
// Tile 128 cols x 64 rows, 256 threads, thread = 4 cols x 8 rows.
// Warp = 128x8 = one full 8x8-block row -> in-warp ratio reduction (1 shfl).
// Image double-buffered in SMEM (ratio applied at read); conductances in
// registers (2 CTAs/SM -> 128-reg cap, 16 warps/SM). 1 syncthreads/iter.
// 256 CTAs co-resident (2/SM); inter-CTA halo via global rings + acq/rel flags.

#define NPIX   (1024*1024)
#define CV_OFF 2097152
#define CH_OFF 4192256
#define GX  8
#define GYn 16
#define NCTA (2*GX*GYn)        // 256

// dynamic SMEM layout (floats)
#define OFF_BUF 0              // [2][64][128] = 16384
#define OFF_RAT 16384          // [2][128]
#define OFF_SRC 16640          // 128
#define OFF_MSK 16768          // 128
#define SMEMF   16896          // 67584 bytes

__device__ float g_shift;
__device__ int   g_flag[NCTA];
__device__ float g_brow[2][2][GYn][2][1024];   // [parity][batch][tyr][top/bot][col]
__device__ float g_bcol[2][2][GX][2][1024];    // [parity][batch][bx][left/right][row]

// ---------------------------------------------------------------------------
__global__ void k_pre(const float* __restrict__ src)
{
    __shared__ float red[32];
    int tid = threadIdx.x;                       // 1024 threads
    float mn = 1e30f;
    for (int i = tid; i < 2*128*128; i += 1024) mn = fminf(mn, src[i]);
    #pragma unroll
    for (int o = 16; o; o >>= 1) mn = fminf(mn, __shfl_xor_sync(~0u, mn, o));
    if ((tid & 31) == 0) red[tid >> 5] = mn;
    __syncthreads();
    if (tid < 32) {
        float v = red[tid];
        #pragma unroll
        for (int o = 16; o; o >>= 1) v = fminf(v, __shfl_xor_sync(~0u, v, o));
        if (tid == 0) g_shift = (v <= 0.1f) ? 0.1f : 0.0f;
    }
    if (tid < NCTA) g_flag[tid] = -1;
}

// ---------------------------------------------------------------------------
__device__ __forceinline__ void spin_ge(const int* p, int t)
{
    int v;
    do {
        asm volatile("ld.acquire.gpu.global.s32 %0, [%1];"
                     : "=r"(v) : "l"(p) : "memory");
    } while (v < t);
}

__device__ __forceinline__ void flag_release(int* p, int val)
{
    int old;
    asm volatile("atom.release.gpu.global.exch.b32 %0, [%1], %2;"
                 : "=r"(old) : "l"(p), "r"(val) : "memory");
}

__device__ __forceinline__ float4 f4mul(float4 a, float s)
{ return make_float4(a.x*s, a.y*s, a.z*s, a.w*s); }

extern __shared__ float sm[];

__global__ void __launch_bounds__(256, 2)
k_diffuse(const float* __restrict__ guide, const float* __restrict__ y,
          const float* __restrict__ src,   const float* __restrict__ mask,
          float* __restrict__ out)
{
    const int tid  = threadIdx.x;
    const int rg   = tid >> 5, lane = tid & 31;      // 8 warps, warp = 128x8 rows
    const int bx = blockIdx.x, tyr = blockIdx.y, b = blockIdx.z;
    const int colbase = bx*128, rowbase = tyr*64;
    const int c0 = lane*4, r0 = rg*8;
    const int gc0 = colbase + c0, gr0 = rowbase + r0;
    const int cid = (b*GYn + tyr)*GX + bx;
    const float shift = g_shift;
    const float K2 = 0.03f*0.03f;

    float4 a[9], cr8[8];
    float  cl8[8];

    // ======================= prologue ======================================
    const float* G0 = guide + b*3*NPIX;
    const float* G1 = G0 + NPIX;
    const float* G2 = G1 + NPIX;
    const float* Yp = y + b*NPIX;

    float4 p0 = {0,0,0,0}, p1 = {0,0,0,0}, p2 = {0,0,0,0}, py = {0,0,0,0};
    #pragma unroll
    for (int j = 0; j < 10; j++) {
        int row = gr0 - 1 + j;
        bool inr = (unsigned)row < 1024u;
        int off = row*1024 + gc0;
        float4 q0 = {0,0,0,0}, q1 = {0,0,0,0}, q2 = {0,0,0,0}, qy = {0,0,0,0};
        if (inr) {
            q0 = *(const float4*)(G0 + off);
            q1 = *(const float4*)(G1 + off);
            q2 = *(const float4*)(G2 + off);
            qy = *(const float4*)(Yp + off);
        }
        if (j >= 1) {
            int brow = row - 1;
            float4 av = {0,0,0,0};
            if ((unsigned)brow < 1023u) {
                float sx = 0.25f*(fabsf(q0.x-p0.x)+fabsf(q1.x-p1.x)+fabsf(q2.x-p2.x)+fabsf(qy.x-py.x));
                float sy = 0.25f*(fabsf(q0.y-p0.y)+fabsf(q1.y-p1.y)+fabsf(q2.y-p2.y)+fabsf(qy.y-py.y));
                float sz = 0.25f*(fabsf(q0.z-p0.z)+fabsf(q1.z-p1.z)+fabsf(q2.z-p2.z)+fabsf(qy.z-py.z));
                float sw = 0.25f*(fabsf(q0.w-p0.w)+fabsf(q1.w-p1.w)+fabsf(q2.w-p2.w)+fabsf(qy.w-py.w));
                float4 cv4 = make_float4(1.f/(1.f + sx*sx/K2), 1.f/(1.f + sy*sy/K2),
                                         1.f/(1.f + sz*sz/K2), 1.f/(1.f + sw*sw/K2));
                if (j >= 2)                            // brow in [gr0, gr0+7]
                    *(float4*)(out + CV_OFF + b*(1023*1024) + brow*1024 + gc0) = cv4;
                av = make_float4(0.24f*cv4.x, 0.24f*cv4.y, 0.24f*cv4.z, 0.24f*cv4.w);
            }
            a[j-1] = av;
        }
        if (j >= 1 && j <= 8) {
            int i = j - 1;                              // local row r0+i
            float4 vv = make_float4(qy.x+shift, qy.y+shift, qy.z+shift, qy.w+shift);
            *(float4*)&sm[OFF_BUF + (r0+i)*128 + c0] = vv;
            if (rg == 0 && i == 0 && tyr > 0)
                *(float4*)&g_brow[0][b][tyr][0][gc0] = vv;
            if (rg == 7 && i == 7 && tyr < GYn-1)
                *(float4*)&g_brow[0][b][tyr][1][gc0] = vv;
            if (lane == 0 && bx > 0)
                g_bcol[0][b][bx][0][rowbase + r0 + i] = vv.x;
            if (lane == 31 && bx < GX-1)
                g_bcol[0][b][bx][1][rowbase + r0 + i] = vv.w;

            float r0s = 0.f, r1s = 0.f, r2s = 0.f, rys = 0.f;
            if (gc0 + 4 < 1024) {
                r0s = G0[off+4]; r1s = G1[off+4]; r2s = G2[off+4]; rys = Yp[off+4];
            }
            float sx = 0.25f*(fabsf(q0.y-q0.x)+fabsf(q1.y-q1.x)+fabsf(q2.y-q2.x)+fabsf(qy.y-qy.x));
            float sy = 0.25f*(fabsf(q0.z-q0.y)+fabsf(q1.z-q1.y)+fabsf(q2.z-q2.y)+fabsf(qy.z-qy.y));
            float sz = 0.25f*(fabsf(q0.w-q0.z)+fabsf(q1.w-q1.z)+fabsf(q2.w-q2.z)+fabsf(qy.w-qy.z));
            float sw = 0.25f*(fabsf(r0s-q0.w)+fabsf(r1s-q1.w)+fabsf(r2s-q2.w)+fabsf(rys-qy.w));
            float chx = 1.f/(1.f + sx*sx/K2);
            float chy = 1.f/(1.f + sy*sy/K2);
            float chz = 1.f/(1.f + sz*sz/K2);
            float chw = (gc0 + 3 < 1023) ? 1.f/(1.f + sw*sw/K2) : 0.f;
            float* cho = out + CH_OFF + b*(1024*1023) + row*1023 + gc0;
            cho[0] = chx; cho[1] = chy; cho[2] = chz;
            if (gc0 + 3 < 1023) cho[3] = chw;
            cr8[i] = make_float4(0.24f*chx, 0.24f*chy, 0.24f*chz, 0.24f*chw);

            float westch = 0.f;
            if (lane == 0 && bx > 0) {
                float l0 = G0[off-1], l1 = G1[off-1], l2 = G2[off-1], ly = Yp[off-1];
                float s = 0.25f*(fabsf(q0.x-l0)+fabsf(q1.x-l1)+fabsf(q2.x-l2)+fabsf(qy.x-ly));
                westch = 0.24f/(1.f + s*s/K2);
            }
            float c = __shfl_up_sync(~0u, cr8[i].w, 1);
            cl8[i] = (lane == 0) ? westch : c;
        }
        p0 = q0; p1 = q1; p2 = q2; py = qy;
    }

    if (tid < 128) {
        // CTA covers 8 block-rows x 16 block-cols
        int br = tid >> 4, bc = tid & 15;
        int bi = b*16384 + ((rowbase>>3) + br)*128 + (colbase>>3) + bc;
        sm[OFF_SRC + tid] = src[bi] + shift;
        sm[OFF_MSK + tid] = (mask[bi] < 0.5f) ? 0.f : 1.f;
        sm[OFF_RAT + tid] = 1.0f;                       // parity-0 ratios
    }
    __syncthreads();
    if (tid == 0) flag_release(&g_flag[cid], 0);

    const bool hw = (bx > 0), he = (bx < GX-1);
    const int bc2 = lane >> 1;                          // block col 0..15
    const int bsel = rg*16 + bc2;

    // ======================= 64 diffusion iterations =======================
    for (int t = 0; t < 64; t++) {
        int par = t & 1, pn = par ^ 1;
        const float ratS = sm[OFF_RAT + par*128 + bsel];

        float4 up;
        if (rg == 0) {
            if (tyr > 0) { spin_ge(&g_flag[cid - GX], t);
                           up = __ldcg((const float4*)&g_brow[par][b][tyr-1][1][gc0]); }
            else up = make_float4(0,0,0,0);
        } else {
            float ru = sm[OFF_RAT + par*128 + bsel - 16];
            up = f4mul(*(const float4*)&sm[OFF_BUF + par*8192 + (r0-1)*128 + c0], ru);
        }
        float4 dnv;
        if (rg == 7) {
            if (tyr < GYn-1) { spin_ge(&g_flag[cid + GX], t);
                               dnv = __ldcg((const float4*)&g_brow[par][b][tyr+1][0][gc0]); }
            else dnv = make_float4(0,0,0,0);
        } else {
            float rd = sm[OFF_RAT + par*128 + bsel + 16];
            dnv = f4mul(*(const float4*)&sm[OFF_BUF + par*8192 + (r0+8)*128 + c0], rd);
        }
        if (lane == 0  && hw) spin_ge(&g_flag[cid - 1], t);
        if (lane == 31 && he) spin_ge(&g_flag[cid + 1], t);
        const float* wr = &g_bcol[par][b][hw ? bx-1 : 0][1][rowbase + r0];
        const float* er = &g_bcol[par][b][he ? bx+1 : 0][0][rowbase + r0];

        float4 pv = up;
        float4 cur = f4mul(*(const float4*)&sm[OFF_BUF + par*8192 + r0*128 + c0], ratS);
        float4 a0 = a[0];
        float acc = 0.f;
        #pragma unroll
        for (int i = 0; i < 8; i++) {
            float4 nxt = (i < 7)
                ? f4mul(*(const float4*)&sm[OFF_BUF + par*8192 + (r0+i+1)*128 + c0], ratS)
                : dnv;
            float lf = __shfl_up_sync(~0u, cur.w, 1);
            if (lane == 0)  lf = hw ? __ldcg(wr + i) : 0.f;
            float rt = __shfl_down_sync(~0u, cur.x, 1);
            if (lane == 31) rt = he ? __ldcg(er + i) : 0.f;
            float4 a1 = a[i+1], c = cr8[i];
            float nx = cur.x + (a1.x*(nxt.x-cur.x) - a0.x*(cur.x-pv.x) + c.x*(cur.y-cur.x) - cl8[i]*(cur.x-lf));
            float ny = cur.y + (a1.y*(nxt.y-cur.y) - a0.y*(cur.y-pv.y) + c.y*(cur.z-cur.y) - c.x*(cur.y-cur.x));
            float nz = cur.z + (a1.z*(nxt.z-cur.z) - a0.z*(cur.z-pv.z) + c.z*(cur.w-cur.z) - c.y*(cur.z-cur.y));
            float nw = cur.w + (a1.w*(nxt.w-cur.w) - a0.w*(cur.w-pv.w) + c.w*(rt   -cur.w) - c.z*(cur.w-cur.z));
            *(float4*)&sm[OFF_BUF + pn*8192 + (r0+i)*128 + c0] = make_float4(nx, ny, nz, nw);
            acc += (nx + ny) + (nz + nw);
            pv = cur; cur = nxt; a0 = a1;
        }

        // 8x8 block sum: warp = one block row, block = 2 adjacent lanes
        float bsum = acc + __shfl_xor_sync(~0u, acc, 1);
        float ratio = (sm[OFF_MSK + bsel] != 0.f)
                    ? __fdividef(sm[OFF_SRC + bsel], bsum*(1.f/64.f) + 1e-8f) : 1.f;
        if (!(lane & 1)) sm[OFF_RAT + pn*128 + bsel] = ratio;

        if (t < 63) {
            // publish pre-scaled rings for t+1 (re-read own stores, same thread)
            if (rg == 0 && tyr > 0) {
                float4 v0 = *(const float4*)&sm[OFF_BUF + pn*8192 + c0];
                __stcg((float4*)&g_brow[pn][b][tyr][0][gc0], f4mul(v0, ratio));
            }
            if (rg == 7 && tyr < GYn-1) {
                float4 v7 = *(const float4*)&sm[OFF_BUF + pn*8192 + 63*128 + c0];
                __stcg((float4*)&g_brow[pn][b][tyr][1][gc0], f4mul(v7, ratio));
            }
            if (lane == 0 && hw) {
                #pragma unroll
                for (int i = 0; i < 8; i++)
                    __stcg(&g_bcol[pn][b][bx][0][rowbase + r0 + i],
                           sm[OFF_BUF + pn*8192 + (r0+i)*128] * ratio);
            }
            if (lane == 31 && he) {
                #pragma unroll
                for (int i = 0; i < 8; i++)
                    __stcg(&g_bcol[pn][b][bx][1][rowbase + r0 + i],
                           sm[OFF_BUF + pn*8192 + (r0+i)*128 + 127] * ratio);
            }
        }
        __syncthreads();
        if (tid == 0 && t < 63) flag_release(&g_flag[cid], t + 1);
    }

    // ======================= epilogue ======================================
    const float ratF = sm[OFF_RAT + 0*128 + bsel];      // pn of t=63 is 0
    #pragma unroll
    for (int i = 0; i < 8; i++) {
        float4 v = *(const float4*)&sm[OFF_BUF + 0*8192 + (r0+i)*128 + c0];
        float4 o = make_float4(v.x*ratF - shift, v.y*ratF - shift,
                               v.z*ratF - shift, v.w*ratF - shift);
        *(float4*)(out + b*NPIX + (gr0 + i)*1024 + gc0) = o;
    }
}

// ---------------------------------------------------------------------------
extern "C" void kernel_launch(void* const* d_in, const int* in_sizes, int n_in,
                              void* d_out, int out_size)
{
    const float* guide = (const float*)d_in[0];
    const float* y     = (const float*)d_in[1];
    const float* src   = (const float*)d_in[2];
    const float* mask  = (const float*)d_in[3];
    float* out = (float*)d_out;

    cudaFuncSetAttribute(k_diffuse, cudaFuncAttributeMaxDynamicSharedMemorySize,
                         SMEMF * sizeof(float));

    k_pre<<<1, 1024>>>(src);
    dim3 g(GX, GYn, 2);                 // 256 CTAs — 2/SM, all co-resident
    k_diffuse<<<g, 256, SMEMF * sizeof(float)>>>(guide, y, src, mask, out);
}

// round 14
// speedup vs baseline: 2.4436x; 1.3854x over previous
#include <cuda_runtime.h>

// GADBase guided anisotropic diffusion — persistent kernel v5b (dynamic smem).
// Tile 128 cols x 32 rows, 128 threads (4 warps), thread = 4 cols x 8 rows.
// Image v[8] (float4) in REGISTERS (32 regs); conductances in SMEM (f32).
// Warp = 128x8 = one 8x8-block row -> in-warp ratio reduction, no barrier.
// 1 syncthreads/iter. 512 CTAs at 4/SM (all co-resident); inter-CTA halo via
// global rings + acquire/release flags; inter-warp rows via parity SMEM buffer.

#define NPIX   (1024*1024)
#define CV_OFF 2097152
#define CH_OFF 4192256
#define GX  8
#define GYT 32
#define NCTA (2*GX*GYT)        // 512

// dynamic SMEM layout (floats)
#define OFF_A   0              // 33*128 = 4224 : 0.24*cv, boundary k above row k
#define OFF_C   4224           // 32*132 = 4224 : 0.24*ch, idx3 = west pad, 4.. cols
#define OFF_BT  8448           // [2][4][2][128] = 2048 : parity row exchange
#define OFF_SRC 10496          // 64
#define OFF_MSK 10560          // 64
#define SMEMF   10624          // 42496 bytes -> 4-5 CTAs/SM by smem

__device__ float g_shift;
__device__ int   g_flag[NCTA];
__device__ float g_brow[2][2][GYT][2][1024];   // [parity][batch][tyr][top/bot][col]
__device__ float g_bcol[2][2][GX][2][1024];    // [parity][batch][bx][left/right][row]

// ---------------------------------------------------------------------------
__global__ void k_pre(const float* __restrict__ src)
{
    __shared__ float red[32];
    int tid = threadIdx.x;                       // 1024 threads
    float mn = 1e30f;
    for (int i = tid; i < 2*128*128; i += 1024) mn = fminf(mn, src[i]);
    #pragma unroll
    for (int o = 16; o; o >>= 1) mn = fminf(mn, __shfl_xor_sync(~0u, mn, o));
    if ((tid & 31) == 0) red[tid >> 5] = mn;
    __syncthreads();
    if (tid < 32) {
        float v = red[tid];
        #pragma unroll
        for (int o = 16; o; o >>= 1) v = fminf(v, __shfl_xor_sync(~0u, v, o));
        if (tid == 0) g_shift = (v <= 0.1f) ? 0.1f : 0.0f;
    }
    if (tid < NCTA) g_flag[tid] = -1;
}

// ---------------------------------------------------------------------------
__device__ __forceinline__ void spin_ge(const int* p, int t)
{
    int v;
    do {
        asm volatile("ld.acquire.gpu.global.s32 %0, [%1];"
                     : "=r"(v) : "l"(p) : "memory");
    } while (v < t);
}

__device__ __forceinline__ void flag_release(int* p, int val)
{
    int old;
    asm volatile("atom.release.gpu.global.exch.b32 %0, [%1], %2;"
                 : "=r"(old) : "l"(p), "r"(val) : "memory");
}

__device__ __forceinline__ float f4pick(float4 v, int i)
{ return i == 0 ? v.x : i == 1 ? v.y : i == 2 ? v.z : v.w; }

extern __shared__ float sm[];

// ---------------------------------------------------------------------------
__global__ void __launch_bounds__(128, 4)
k_diffuse(const float* __restrict__ guide, const float* __restrict__ y,
          const float* __restrict__ src,   const float* __restrict__ mask,
          float* __restrict__ out)
{
    const int tid  = threadIdx.x;
    const int w    = tid >> 5, lane = tid & 31;      // 4 warps, warp = 128x8
    const int bx = blockIdx.x, tyr = blockIdx.y, b = blockIdx.z;
    const int colbase = bx*128, rowbase = tyr*32;
    const int c0 = lane*4, r0 = w*8;
    const int gc0 = colbase + c0, gr0 = rowbase + r0;
    const int cid = (b*GYT + tyr)*GX + bx;
    const float shift = g_shift;
    const float K2 = 0.03f*0.03f;

    float4 v[8];

    // ======================= prologue ======================================
    const float* G0 = guide + b*3*NPIX;
    const float* G1 = G0 + NPIX;
    const float* G2 = G1 + NPIX;
    const float* Yp = y + b*NPIX;

    float4 p0 = {0,0,0,0}, p1 = {0,0,0,0}, p2 = {0,0,0,0}, py = {0,0,0,0};
    #pragma unroll
    for (int j = 0; j < 10; j++) {
        int row = gr0 - 1 + j;
        bool inr = (unsigned)row < 1024u;
        int off = row*1024 + gc0;
        float4 q0 = {0,0,0,0}, q1 = {0,0,0,0}, q2 = {0,0,0,0}, qy = {0,0,0,0};
        if (inr) {
            q0 = *(const float4*)(G0 + off);
            q1 = *(const float4*)(G1 + off);
            q2 = *(const float4*)(G2 + off);
            qy = *(const float4*)(Yp + off);
        }
        if (j >= 1) {
            int brow = row - 1;                         // boundary (brow, brow+1)
            float4 av = {0,0,0,0};
            if ((unsigned)brow < 1023u) {
                float sx = 0.25f*(fabsf(q0.x-p0.x)+fabsf(q1.x-p1.x)+fabsf(q2.x-p2.x)+fabsf(qy.x-py.x));
                float sy = 0.25f*(fabsf(q0.y-p0.y)+fabsf(q1.y-p1.y)+fabsf(q2.y-p2.y)+fabsf(qy.y-py.y));
                float sz = 0.25f*(fabsf(q0.z-p0.z)+fabsf(q1.z-p1.z)+fabsf(q2.z-p2.z)+fabsf(qy.z-py.z));
                float sw = 0.25f*(fabsf(q0.w-p0.w)+fabsf(q1.w-p1.w)+fabsf(q2.w-p2.w)+fabsf(qy.w-py.w));
                float4 cv4 = make_float4(1.f/(1.f + sx*sx/K2), 1.f/(1.f + sy*sy/K2),
                                         1.f/(1.f + sz*sz/K2), 1.f/(1.f + sw*sw/K2));
                if (j >= 2)                            // ownership: brow in [gr0, gr0+7]
                    *(float4*)(out + CV_OFF + b*(1023*1024) + brow*1024 + gc0) = cv4;
                av = make_float4(0.24f*cv4.x, 0.24f*cv4.y, 0.24f*cv4.z, 0.24f*cv4.w);
            }
            *(float4*)&sm[OFF_A + (r0 + j - 1)*128 + c0] = av;
        }
        if (j >= 1 && j <= 8) {
            int i = j - 1;                              // local row r0+i
            v[i] = make_float4(qy.x+shift, qy.y+shift, qy.z+shift, qy.w+shift);

            float r0s = 0.f, r1s = 0.f, r2s = 0.f, rys = 0.f;
            if (gc0 + 4 < 1024) {
                r0s = G0[off+4]; r1s = G1[off+4]; r2s = G2[off+4]; rys = Yp[off+4];
            }
            float sx = 0.25f*(fabsf(q0.y-q0.x)+fabsf(q1.y-q1.x)+fabsf(q2.y-q2.x)+fabsf(qy.y-qy.x));
            float sy = 0.25f*(fabsf(q0.z-q0.y)+fabsf(q1.z-q1.y)+fabsf(q2.z-q2.y)+fabsf(qy.z-qy.y));
            float sz = 0.25f*(fabsf(q0.w-q0.z)+fabsf(q1.w-q1.z)+fabsf(q2.w-q2.z)+fabsf(qy.w-qy.z));
            float sw = 0.25f*(fabsf(r0s-q0.w)+fabsf(r1s-q1.w)+fabsf(r2s-q2.w)+fabsf(rys-qy.w));
            float chx = 1.f/(1.f + sx*sx/K2);
            float chy = 1.f/(1.f + sy*sy/K2);
            float chz = 1.f/(1.f + sz*sz/K2);
            float chw = (gc0 + 3 < 1023) ? 1.f/(1.f + sw*sw/K2) : 0.f;
            float* cho = out + CH_OFF + b*(1024*1023) + row*1023 + gc0;
            cho[0] = chx; cho[1] = chy; cho[2] = chz;
            if (gc0 + 3 < 1023) cho[3] = chw;
            *(float4*)&sm[OFF_C + (r0+i)*132 + 4 + c0] =
                make_float4(0.24f*chx, 0.24f*chy, 0.24f*chz, 0.24f*chw);
            if (lane == 0) {
                float westch = 0.f;
                if (bx > 0) {
                    float l0 = G0[off-1], l1 = G1[off-1], l2 = G2[off-1], ly = Yp[off-1];
                    float s = 0.25f*(fabsf(q0.x-l0)+fabsf(q1.x-l1)+fabsf(q2.x-l2)+fabsf(qy.x-ly));
                    westch = 0.24f/(1.f + s*s/K2);
                }
                sm[OFF_C + (r0+i)*132 + 3] = westch;
            }
        }
        p0 = q0; p1 = q1; p2 = q2; py = qy;
    }

    if (tid < 64) {                                     // 4 block-rows x 16 block-cols
        int br = tid >> 4, bc = tid & 15;
        int bi = b*16384 + ((rowbase>>3) + br)*128 + (colbase>>3) + bc;
        sm[OFF_SRC + tid] = src[bi] + shift;
        sm[OFF_MSK + tid] = (mask[bi] < 0.5f) ? 0.f : 1.f;
    }

    const bool hw = (bx > 0), he = (bx < GX-1);

    // state-0 boundary publishes (parity 0)
    *(float4*)&sm[OFF_BT + ((0*4 + w)*2 + 0)*128 + c0] = v[0];
    *(float4*)&sm[OFF_BT + ((0*4 + w)*2 + 1)*128 + c0] = v[7];
    if (w == 0 && tyr > 0)       *(float4*)&g_brow[0][b][tyr][0][gc0] = v[0];
    if (w == 3 && tyr < GYT-1)   *(float4*)&g_brow[0][b][tyr][1][gc0] = v[7];
    if (lane == 0 && hw) {
        float* d = &g_bcol[0][b][bx][0][rowbase + r0];
        *(float4*)d       = make_float4(v[0].x, v[1].x, v[2].x, v[3].x);
        *(float4*)(d + 4) = make_float4(v[4].x, v[5].x, v[6].x, v[7].x);
    }
    if (lane == 31 && he) {
        float* d = &g_bcol[0][b][bx][1][rowbase + r0];
        *(float4*)d       = make_float4(v[0].w, v[1].w, v[2].w, v[3].w);
        *(float4*)(d + 4) = make_float4(v[4].w, v[5].w, v[6].w, v[7].w);
    }
    __syncthreads();
    if (tid == 0) flag_release(&g_flag[cid], 0);

    const int bsel = w*16 + (lane >> 1);
    const float b_src = sm[OFF_SRC + bsel];
    const float b_msk = sm[OFF_MSK + bsel];

    // ======================= 64 diffusion iterations =======================
    for (int t = 0; t < 64; t++) {
        int par = t & 1, pn = par ^ 1;

        // vertical halo rows
        float4 up;
        if (w == 0) {
            if (tyr > 0) { spin_ge(&g_flag[cid - GX], t);
                           up = __ldcg((const float4*)&g_brow[par][b][tyr-1][1][gc0]); }
            else up = make_float4(0,0,0,0);
        } else up = *(const float4*)&sm[OFF_BT + ((par*4 + w - 1)*2 + 1)*128 + c0];
        float4 dn;
        if (w == 3) {
            if (tyr < GYT-1) { spin_ge(&g_flag[cid + GX], t);
                               dn = __ldcg((const float4*)&g_brow[par][b][tyr+1][0][gc0]); }
            else dn = make_float4(0,0,0,0);
        } else dn = *(const float4*)&sm[OFF_BT + ((par*4 + w + 1)*2 + 0)*128 + c0];

        // side edge columns: hoisted 2x LDG.128 per edge lane
        float4 le0 = {0,0,0,0}, le1 = {0,0,0,0}, re0 = {0,0,0,0}, re1 = {0,0,0,0};
        if (lane == 0 && hw) {
            spin_ge(&g_flag[cid - 1], t);
            const float4* wr = (const float4*)&g_bcol[par][b][bx-1][1][rowbase + r0];
            le0 = __ldcg(wr); le1 = __ldcg(wr + 1);
        }
        if (lane == 31 && he) {
            spin_ge(&g_flag[cid + 1], t);
            const float4* er = (const float4*)&g_bcol[par][b][bx+1][0][rowbase + r0];
            re0 = __ldcg(er); re1 = __ldcg(er + 1);
        }

        // stencil (register chain down the 8 rows)
        float4 pv = up;
        float4 a0 = *(const float4*)&sm[OFF_A + r0*128 + c0];
        float acc = 0.f;
        #pragma unroll
        for (int i = 0; i < 8; i++) {
            float4 cur = v[i];
            float4 nxt = (i < 7) ? v[i+1] : dn;
            float4 a1 = *(const float4*)&sm[OFF_A + (r0+i+1)*128 + c0];
            float4 c  = *(const float4*)&sm[OFF_C + (r0+i)*132 + 4 + c0];
            float  cl = sm[OFF_C + (r0+i)*132 + 3 + c0];
            float lf = __shfl_up_sync(~0u, cur.w, 1);
            if (lane == 0)  lf = (i < 4) ? f4pick(le0, i) : f4pick(le1, i-4);
            float rt = __shfl_down_sync(~0u, cur.x, 1);
            if (lane == 31) rt = (i < 4) ? f4pick(re0, i) : f4pick(re1, i-4);
            float nx = cur.x + (a1.x*(nxt.x-cur.x) - a0.x*(cur.x-pv.x) + c.x*(cur.y-cur.x) - cl *(cur.x-lf));
            float ny = cur.y + (a1.y*(nxt.y-cur.y) - a0.y*(cur.y-pv.y) + c.y*(cur.z-cur.y) - c.x*(cur.y-cur.x));
            float nz = cur.z + (a1.z*(nxt.z-cur.z) - a0.z*(cur.z-pv.z) + c.z*(cur.w-cur.z) - c.y*(cur.z-cur.y));
            float nw = cur.w + (a1.w*(nxt.w-cur.w) - a0.w*(cur.w-pv.w) + c.w*(rt   -cur.w) - c.z*(cur.w-cur.z));
            v[i] = make_float4(nx, ny, nz, nw);
            acc += (nx + ny) + (nz + nw);
            pv = cur; a0 = a1;
        }

        // 8x8 block sum: warp = one block row; block = 2 adjacent lanes
        float bsum = acc + __shfl_xor_sync(~0u, acc, 1);
        float ratio = (b_msk != 0.f)
                    ? __fdividef(b_src, bsum*(1.f/64.f) + 1e-8f) : 1.f;
        #pragma unroll
        for (int i = 0; i < 8; i++) {
            v[i].x *= ratio; v[i].y *= ratio; v[i].z *= ratio; v[i].w *= ratio;
        }

        if (t == 63) break;

        // publish state t+1 boundaries
        *(float4*)&sm[OFF_BT + ((pn*4 + w)*2 + 0)*128 + c0] = v[0];
        *(float4*)&sm[OFF_BT + ((pn*4 + w)*2 + 1)*128 + c0] = v[7];
        if (w == 0 && tyr > 0)     __stcg((float4*)&g_brow[pn][b][tyr][0][gc0], v[0]);
        if (w == 3 && tyr < GYT-1) __stcg((float4*)&g_brow[pn][b][tyr][1][gc0], v[7]);
        if (lane == 0 && hw) {
            float* d = &g_bcol[pn][b][bx][0][rowbase + r0];
            __stcg((float4*)d,       make_float4(v[0].x, v[1].x, v[2].x, v[3].x));
            __stcg((float4*)(d + 4), make_float4(v[4].x, v[5].x, v[6].x, v[7].x));
        }
        if (lane == 31 && he) {
            float* d = &g_bcol[pn][b][bx][1][rowbase + r0];
            __stcg((float4*)d,       make_float4(v[0].w, v[1].w, v[2].w, v[3].w));
            __stcg((float4*)(d + 4), make_float4(v[4].w, v[5].w, v[6].w, v[7].w));
        }
        __syncthreads();                 // CTA publishes done (cumulative for release)
        if (tid == 0) flag_release(&g_flag[cid], t + 1);
    }

    // ======================= epilogue ======================================
    #pragma unroll
    for (int i = 0; i < 8; i++) {
        float4 o = make_float4(v[i].x - shift, v[i].y - shift,
                               v[i].z - shift, v[i].w - shift);
        *(float4*)(out + b*NPIX + (gr0 + i)*1024 + gc0) = o;
    }
}

// ---------------------------------------------------------------------------
extern "C" void kernel_launch(void* const* d_in, const int* in_sizes, int n_in,
                              void* d_out, int out_size)
{
    const float* guide = (const float*)d_in[0];
    const float* y     = (const float*)d_in[1];
    const float* src   = (const float*)d_in[2];
    const float* mask  = (const float*)d_in[3];
    float* out = (float*)d_out;

    cudaFuncSetAttribute(k_diffuse, cudaFuncAttributeMaxDynamicSharedMemorySize,
                         SMEMF * sizeof(float));

    k_pre<<<1, 1024>>>(src);
    dim3 g(GX, GYT, 2);                 // 512 CTAs — 4/SM, all co-resident
    k_diffuse<<<g, 128, SMEMF * sizeof(float)>>>(guide, y, src, mask, out);
}